// round 2
// baseline (speedup 1.0000x reference)
#include <cuda_runtime.h>
#include <cuda_bf16.h>

#define POOL 7
#define C 256

__global__ __launch_bounds__(256) void roi_align_kernel(
    const float* __restrict__ boxes,
    const float* __restrict__ meta,
    const float* __restrict__ f2,
    const float* __restrict__ f3,
    const float* __restrict__ f4,
    const float* __restrict__ f5,
    float* __restrict__ out,
    int N)
{
    const int box_id = blockIdx.x;         // 0 .. B*N-1
    const int batch  = box_id / N;
    const int tid    = threadIdx.x;

    __shared__ int   s_y0[POOL], s_y1[POOL], s_x0[POOL], s_x1[POOL];
    __shared__ float s_fy[POOL], s_fx[POOL];

    // --- per-box scalars (computed redundantly; cheap) ---
    const float by1 = boxes[box_id * 4 + 0];
    const float bx1 = boxes[box_id * 4 + 1];
    const float by2 = boxes[box_id * 4 + 2];
    const float bx2 = boxes[box_id * 4 + 3];

    const float h = by2 - by1;
    const float w = bx2 - bx1;
    const float area = meta[4] * meta[5];
    // lvl = log2(sqrt(h*w) / (224/sqrt(area)));  roi_level = clip(4 + round(lvl), 2, 5)
    const float lvl = log2f(sqrtf(h * w) / (224.0f / sqrtf(area)));
    float lv = 4.0f + rintf(lvl);             // rintf = round-half-to-even = jnp.round
    lv = fminf(fmaxf(lv, 2.0f), 5.0f);
    const int level = (int)lv;

    int Hs;
    const float* f;
    if (level == 2)      { Hs = 256; f = f2; }
    else if (level == 3) { Hs = 128; f = f3; }
    else if (level == 4) { Hs = 64;  f = f4; }
    else                 { Hs = 32;  f = f5; }
    const int Ws = Hs;
    const float* base = f + (size_t)batch * Hs * Ws * C;

    // --- sample coordinates (7 y by threads 0..6, 7 x by threads 7..13) ---
    if (tid < POOL) {
        const int i = tid;
        const float step = (by2 - by1) * (float)(Hs - 1) / (float)(POOL - 1);
        const float ys   = by1 * (float)(Hs - 1) + (float)i * step;
        const float y0f  = floorf(ys);
        int y0 = (int)y0f;
        y0 = min(max(y0, 0), Hs - 1);
        s_y0[i] = y0;
        s_y1[i] = min(y0 + 1, Hs - 1);
        s_fy[i] = ys - y0f;
    } else if (tid < 2 * POOL) {
        const int i = tid - POOL;
        const float step = (bx2 - bx1) * (float)(Ws - 1) / (float)(POOL - 1);
        const float xs   = bx1 * (float)(Ws - 1) + (float)i * step;
        const float x0f  = floorf(xs);
        int x0 = (int)x0f;
        x0 = min(max(x0, 0), Ws - 1);
        s_x0[i] = x0;
        s_x1[i] = min(x0 + 1, Ws - 1);
        s_fx[i] = xs - x0f;
    }
    __syncthreads();

    // --- main loop: 64 lanes x float4 cover C=256; 4 cells in flight ---
    const int ch    = (tid & 63) * 4;   // channel offset
    const int cell0 = tid >> 6;         // 0..3
    float* obase = out + ((size_t)box_id * (POOL * POOL)) * C + ch;

    #pragma unroll 1
    for (int cell = cell0; cell < POOL * POOL; cell += 4) {
        const int py = cell / POOL;
        const int px = cell - py * POOL;
        const int y0 = s_y0[py], y1i = s_y1[py];
        const int x0 = s_x0[px], x1i = s_x1[px];
        const float fy = s_fy[py], fx = s_fx[px];

        const float4 tl = *(const float4*)(base + ((y0  * Ws + x0 ) * C + ch));
        const float4 tr = *(const float4*)(base + ((y0  * Ws + x1i) * C + ch));
        const float4 bl = *(const float4*)(base + ((y1i * Ws + x0 ) * C + ch));
        const float4 br = *(const float4*)(base + ((y1i * Ws + x1i) * C + ch));

        float4 o;
        {
            float top = tl.x + (tr.x - tl.x) * fx;
            float bot = bl.x + (br.x - bl.x) * fx;
            o.x = top + (bot - top) * fy;
        }
        {
            float top = tl.y + (tr.y - tl.y) * fx;
            float bot = bl.y + (br.y - bl.y) * fx;
            o.y = top + (bot - top) * fy;
        }
        {
            float top = tl.z + (tr.z - tl.z) * fx;
            float bot = bl.z + (br.z - bl.z) * fx;
            o.z = top + (bot - top) * fy;
        }
        {
            float top = tl.w + (tr.w - tl.w) * fx;
            float bot = bl.w + (br.w - bl.w) * fx;
            o.w = top + (bot - top) * fy;
        }

        *(float4*)(obase + (size_t)cell * C) = o;
    }
}

extern "C" void kernel_launch(void* const* d_in, const int* in_sizes, int n_in,
                              void* d_out, int out_size) {
    const float* boxes = (const float*)d_in[0];
    const float* meta  = (const float*)d_in[1];
    const float* f2    = (const float*)d_in[2];
    const float* f3    = (const float*)d_in[3];
    const float* f4    = (const float*)d_in[4];
    const float* f5    = (const float*)d_in[5];
    float* out = (float*)d_out;

    const int BN = in_sizes[0] / 4;                    // total boxes = B*N
    const int B  = in_sizes[2] / (256 * 256 * 256);    // feat2 = B*256*256*C
    const int N  = BN / B;

    roi_align_kernel<<<BN, 256>>>(boxes, meta, f2, f3, f4, f5, out, N);
}

// round 3
// speedup vs baseline: 1.1611x; 1.1611x over previous
#include <cuda_runtime.h>
#include <cuda_bf16.h>

#define POOL 7
#define NCELL 49
#define C 256

__global__ __launch_bounds__(256) void roi_align_kernel(
    const float* __restrict__ boxes,
    const float* __restrict__ meta,
    const float* __restrict__ f2,
    const float* __restrict__ f3,
    const float* __restrict__ f4,
    const float* __restrict__ f5,
    float* __restrict__ out,
    int N)
{
    const int box_id = blockIdx.x;         // 0 .. B*N-1
    const int batch  = box_id / N;
    const int tid    = threadIdx.x;

    // Per-cell descriptors: packed element offsets of the 4 corners (+frac weights)
    __shared__ int4   s_off[NCELL];
    __shared__ float2 s_frac[NCELL];       // {fx, fy}

    // --- per-box scalars (redundant per thread; cheap) ---
    const float by1 = boxes[box_id * 4 + 0];
    const float bx1 = boxes[box_id * 4 + 1];
    const float by2 = boxes[box_id * 4 + 2];
    const float bx2 = boxes[box_id * 4 + 3];

    const float area = meta[4] * meta[5];
    const float lvl  = log2f(sqrtf((by2 - by1) * (bx2 - bx1)) / (224.0f / sqrtf(area)));
    float lv = 4.0f + rintf(lvl);          // rintf = round-half-even = jnp.round
    lv = fminf(fmaxf(lv, 2.0f), 5.0f);
    const int level = (int)lv;

    int Hs;
    const float* f;
    if (level == 2)      { Hs = 256; f = f2; }
    else if (level == 3) { Hs = 128; f = f3; }
    else if (level == 4) { Hs = 64;  f = f4; }
    else                 { Hs = 32;  f = f5; }
    const int Ws = Hs;
    const float* base = f + (size_t)batch * Hs * Ws * C;

    // --- build the 49 cell descriptors (one thread per cell) ---
    if (tid < NCELL) {
        const int py = tid / POOL;
        const int px = tid - py * POOL;

        const float ys = by1 * (float)(Hs - 1)
                       + (float)py * ((by2 - by1) * (float)(Hs - 1) / (float)(POOL - 1));
        const float xs = bx1 * (float)(Ws - 1)
                       + (float)px * ((bx2 - bx1) * (float)(Ws - 1) / (float)(POOL - 1));

        const float y0f = floorf(ys);
        const float x0f = floorf(xs);
        int y0 = min(max((int)y0f, 0), Hs - 1);
        int x0 = min(max((int)x0f, 0), Ws - 1);
        const int y1 = min(y0 + 1, Hs - 1);
        const int x1 = min(x0 + 1, Ws - 1);

        s_off[tid]  = make_int4((y0 * Ws + x0) * C, (y0 * Ws + x1) * C,
                                (y1 * Ws + x0) * C, (y1 * Ws + x1) * C);
        s_frac[tid] = make_float2(xs - x0f, ys - y0f);
    }
    __syncthreads();

    // --- main loop: 64 lanes x float4 cover C=256; 4 cell-groups; 2 cells/iter ---
    const int ch = (tid & 63) * 4;         // channel offset
    const int g  = tid >> 6;               // cell group 0..3
    const float* bch   = base + ch;
    float*       obase = out + (size_t)box_id * (NCELL * C) + ch;

    auto do_cell = [&](int cell) {
        const int4   off = s_off[cell];
        const float2 fr  = s_frac[cell];

        const float4 tl = *(const float4*)(bch + off.x);
        const float4 tr = *(const float4*)(bch + off.y);
        const float4 bl = *(const float4*)(bch + off.z);
        const float4 br = *(const float4*)(bch + off.w);

        float4 o;
        {
            const float top = tl.x + (tr.x - tl.x) * fr.x;
            const float bot = bl.x + (br.x - bl.x) * fr.x;
            o.x = top + (bot - top) * fr.y;
        }
        {
            const float top = tl.y + (tr.y - tl.y) * fr.x;
            const float bot = bl.y + (br.y - bl.y) * fr.x;
            o.y = top + (bot - top) * fr.y;
        }
        {
            const float top = tl.z + (tr.z - tl.z) * fr.x;
            const float bot = bl.z + (br.z - bl.z) * fr.x;
            o.z = top + (bot - top) * fr.y;
        }
        {
            const float top = tl.w + (tr.w - tl.w) * fr.x;
            const float bot = bl.w + (br.w - bl.w) * fr.x;
            o.w = top + (bot - top) * fr.y;
        }
        __stwt((float4*)(obase + (size_t)cell * C), o);  // streaming: keep L2 for reads
    };

    // groups 0..3 cover cells g+4k; process two independent cells per iteration
    #pragma unroll 1
    for (int k = 0; k < 6; k++) {
        const int c0 = g + 8 * k;
        do_cell(c0);
        do_cell(c0 + 4);
    }
    if (g == 0) do_cell(48);
}

extern "C" void kernel_launch(void* const* d_in, const int* in_sizes, int n_in,
                              void* d_out, int out_size) {
    const float* boxes = (const float*)d_in[0];
    const float* meta  = (const float*)d_in[1];
    const float* f2    = (const float*)d_in[2];
    const float* f3    = (const float*)d_in[3];
    const float* f4    = (const float*)d_in[4];
    const float* f5    = (const float*)d_in[5];
    float* out = (float*)d_out;

    const int BN = in_sizes[0] / 4;                    // total boxes = B*N
    const int B  = in_sizes[2] / (256 * 256 * 256);    // feat2 = B*256*256*C
    const int N  = BN / B;

    roi_align_kernel<<<BN, 256>>>(boxes, meta, f2, f3, f4, f5, out, N);
}